// round 1
// baseline (speedup 1.0000x reference)
#include <cuda_runtime.h>
#include <cuda_bf16.h>
#include <math.h>

// Problem constants
#define BB   512   // batch
#define TT   128   // time steps
#define FF   256   // features
#define HH   512   // hidden
#define KK   3     // fuzzy rules

typedef unsigned long long ull;

// ------------------------------------------------------------------
// Device scratch (allocation-free: __device__ globals)
// ------------------------------------------------------------------
__device__ float g_xw[(size_t)TT * BB * HH];   // [T][B][H]  xw = x*w @ Wx  (128 MB)
__device__ float g_h[2][(size_t)BB * HH];      // ping-pong hidden state
__device__ float g_Wxs[FF * HH];               // diag(sigmoid(theta)) @ Wx
__device__ float g_invden[HH * KK];            // 1/(2*sigma^2 + 1e-8)

// ------------------------------------------------------------------
// Packed f32x2 helpers (FFMA2 path — 2x fp32 MAC rate on sm_103a)
// ------------------------------------------------------------------
__device__ __forceinline__ ull pack2(float x, float y) {
    ull r; asm("mov.b64 %0, {%1, %2};" : "=l"(r) : "f"(x), "f"(y)); return r;
}
__device__ __forceinline__ float2 unpack2(ull v) {
    float2 r; asm("mov.b64 {%0, %1}, %2;" : "=f"(r.x), "=f"(r.y) : "l"(v)); return r;
}
__device__ __forceinline__ ull fma2(ull a, ull b, ull c) {
    ull d; asm("fma.rn.f32x2 %0, %1, %2, %3;" : "=l"(d) : "l"(a), "l"(b), "l"(c)); return d;
}

__device__ __forceinline__ float sigmoidf_fast(float x) {
    return 1.0f / (1.0f + __expf(-x));
}

// ------------------------------------------------------------------
// Prep: weights=sigmoid(theta) -> out[512..767], Wxs = w[f]*Wx[f,h],
//       invden = 1/(2 sigma^2 + 1e-8), zero h[0] (must re-zero every replay)
// ------------------------------------------------------------------
__global__ void prep_kernel(const float* __restrict__ theta,
                            const float* __restrict__ Wx,
                            const float* __restrict__ sigma,
                            float* __restrict__ out)
{
    int idx = blockIdx.x * blockDim.x + threadIdx.x;       // 262144 threads
    if (idx < BB * HH) g_h[0][idx] = 0.0f;
    if (idx < FF * HH) {
        int f = idx >> 9;  // /HH
        float w = 1.0f / (1.0f + expf(-theta[f]));
        g_Wxs[idx] = w * Wx[idx];
    }
    if (idx < FF) out[BB + idx] = 1.0f / (1.0f + expf(-theta[idx]));
    if (idx < HH * KK) {
        float s = sigma[idx];
        g_invden[idx] = 1.0f / (2.0f * s * s + 1e-8f);
    }
}

// ------------------------------------------------------------------
// GEMM1: g_xw[t][b][h] = sum_f x[b][t][f] * Wxs[f][h]
// M = B*T = 65536 (row m = b*T + t), N = 512, K = 256
// Tile 128x128, BK=16, 256 threads, 8x8 microtile, M-packed f32x2 accum.
// ------------------------------------------------------------------
__global__ void __launch_bounds__(256) gemm1_kernel(const float* __restrict__ x)
{
    __shared__ float sA[16][130];   // [k][m] transposed, padded
    __shared__ float sB[16][128];   // [k][n]

    const int tid = threadIdx.x;
    const int m0  = blockIdx.x * 128;   // gridDim.x = 512
    const int n0  = blockIdx.y * 128;   // gridDim.y = 4

    // A (x) staging: 128 rows x 16 k; thread loads 8 consecutive k of one row
    const int ar = tid >> 1;            // 0..127
    const int ak = (tid & 1) * 8;       // 0 or 8
    // B (Wxs) staging: 16 k-rows x 128 n; thread loads 8 consecutive n
    const int bk = tid >> 4;            // 0..15
    const int bc = (tid & 15) * 8;      // 0..120

    const float* Ag = x     + (size_t)(m0 + ar) * FF + ak;
    const float* Bg = g_Wxs + (size_t)bk * HH + n0 + bc;

    float4 ra0 = *(const float4*)(Ag);
    float4 ra1 = *(const float4*)(Ag + 4);
    float4 rb0 = *(const float4*)(Bg);
    float4 rb1 = *(const float4*)(Bg + 4);

    ull acc[4][8];
    #pragma unroll
    for (int i = 0; i < 4; ++i)
        #pragma unroll
        for (int j = 0; j < 8; ++j) acc[i][j] = 0ull;

    const int ty = tid >> 4;   // 0..15 : rows ty*8 .. ty*8+7
    const int tx = tid & 15;   // 0..15 : cols tx*8 .. tx*8+7

    #pragma unroll 1
    for (int kt = 0; kt < FF / 16; ++kt) {
        // store staged tile
        sA[ak + 0][ar] = ra0.x; sA[ak + 1][ar] = ra0.y;
        sA[ak + 2][ar] = ra0.z; sA[ak + 3][ar] = ra0.w;
        sA[ak + 4][ar] = ra1.x; sA[ak + 5][ar] = ra1.y;
        sA[ak + 6][ar] = ra1.z; sA[ak + 7][ar] = ra1.w;
        *(float4*)&sB[bk][bc]     = rb0;
        *(float4*)&sB[bk][bc + 4] = rb1;
        __syncthreads();

        // prefetch next k-tile into registers
        if (kt < FF / 16 - 1) {
            const float* Ag2 = Ag + (kt + 1) * 16;
            const float* Bg2 = Bg + (size_t)(kt + 1) * 16 * HH;
            ra0 = *(const float4*)(Ag2);
            ra1 = *(const float4*)(Ag2 + 4);
            rb0 = *(const float4*)(Bg2);
            rb1 = *(const float4*)(Bg2 + 4);
        }

        #pragma unroll
        for (int kk = 0; kk < 16; ++kk) {
            ull a2[4];
            #pragma unroll
            for (int i = 0; i < 4; ++i)
                a2[i] = *(const ull*)&sA[kk][ty * 8 + 2 * i];
            float bf[8];
            *(float4*)&bf[0] = *(const float4*)&sB[kk][tx * 8];
            *(float4*)&bf[4] = *(const float4*)&sB[kk][tx * 8 + 4];
            #pragma unroll
            for (int j = 0; j < 8; ++j) {
                ull bbv = pack2(bf[j], bf[j]);
                #pragma unroll
                for (int i = 0; i < 4; ++i)
                    acc[i][j] = fma2(a2[i], bbv, acc[i][j]);
            }
        }
        __syncthreads();
    }

    // Epilogue: write to g_xw with [t][b][h] layout
    #pragma unroll
    for (int i = 0; i < 4; ++i) {
        float2 v[8];
        #pragma unroll
        for (int j = 0; j < 8; ++j) v[j] = unpack2(acc[i][j]);
        #pragma unroll
        for (int p = 0; p < 2; ++p) {
            int m = m0 + ty * 8 + 2 * i + p;
            int t = m & (TT - 1);
            int b = m >> 7;     // /TT
            float* orow = g_xw + ((size_t)t * BB + b) * HH + n0 + tx * 8;
            float4 o0, o1;
            if (p == 0) {
                o0 = make_float4(v[0].x, v[1].x, v[2].x, v[3].x);
                o1 = make_float4(v[4].x, v[5].x, v[6].x, v[7].x);
            } else {
                o0 = make_float4(v[0].y, v[1].y, v[2].y, v[3].y);
                o1 = make_float4(v[4].y, v[5].y, v[6].y, v[7].y);
            }
            *(float4*)(orow)     = o0;
            *(float4*)(orow + 4) = o1;
        }
    }
}

// ------------------------------------------------------------------
// Step kernel (one per t): Z = xw_t + h_in @ Wh + b, fuzzy gate, h update.
// GEMM tile 32(batch) x 64(hidden), K=512, 256 threads, 2x4 microtile.
// Grid 16 x 8 = 128 blocks. h ping-pongs: read g_h[t&1], write g_h[(t+1)&1].
// ------------------------------------------------------------------
__global__ void __launch_bounds__(256) step_kernel(const float* __restrict__ Wh,
                                                   const float* __restrict__ bias,
                                                   const float* __restrict__ cC,
                                                   const float* __restrict__ qQ,
                                                   int t)
{
    __shared__ float sA[16][34];   // [k][batch-row], padded
    __shared__ float sB[16][64];   // [k][hidden-col]

    const int tid = threadIdx.x;
    const int m0  = blockIdx.x * 32;   // gridDim.x = 16
    const int n0  = blockIdx.y * 64;   // gridDim.y = 8

    const float* hin  = g_h[t & 1];
    float*       hout = g_h[(t + 1) & 1];

    // A staging: 32 rows x 16 k ; thread loads float2 along k
    const int ar = tid >> 3;            // 0..31
    const int ak = (tid & 7) * 2;       // 0..14
    // B staging: 16 k x 64 n ; thread loads float4 along n
    const int bk = tid >> 4;            // 0..15
    const int bc = (tid & 15) * 4;      // 0..60

    const float* Ag = hin + (size_t)(m0 + ar) * HH + ak;
    const float* Bg = Wh  + (size_t)bk * HH + n0 + bc;

    float2 ra = *(const float2*)(Ag);
    float4 rb = *(const float4*)(Bg);

    ull acc[4] = {0ull, 0ull, 0ull, 0ull};

    const int ty = tid >> 4;   // 0..15 : rows ty*2, ty*2+1
    const int tx = tid & 15;   // 0..15 : cols tx*4 .. +3

    #pragma unroll 1
    for (int kt = 0; kt < HH / 16; ++kt) {
        sA[ak][ar]     = ra.x;
        sA[ak + 1][ar] = ra.y;
        *(float4*)&sB[bk][bc] = rb;
        __syncthreads();

        if (kt < HH / 16 - 1) {
            ra = *(const float2*)(Ag + (kt + 1) * 16);
            rb = *(const float4*)(Bg + (size_t)(kt + 1) * 16 * HH);
        }

        #pragma unroll
        for (int kk = 0; kk < 16; ++kk) {
            ull a2 = *(const ull*)&sA[kk][ty * 2];
            float4 bv = *(const float4*)&sB[kk][tx * 4];
            acc[0] = fma2(a2, pack2(bv.x, bv.x), acc[0]);
            acc[1] = fma2(a2, pack2(bv.y, bv.y), acc[1]);
            acc[2] = fma2(a2, pack2(bv.z, bv.z), acc[2]);
            acc[3] = fma2(a2, pack2(bv.w, bv.w), acc[3]);
        }
        __syncthreads();
    }

    // Fused fuzzy-gate epilogue
    const int row0 = m0 + ty * 2;
    const int col0 = n0 + tx * 4;
    const float* xwt = g_xw + (size_t)t * BB * HH;

    #pragma unroll
    for (int j = 0; j < 4; ++j) {
        const int col = col0 + j;
        const float c0 = cC[col * 3 + 0], c1 = cC[col * 3 + 1], c2 = cC[col * 3 + 2];
        const float i0 = g_invden[col * 3 + 0], i1 = g_invden[col * 3 + 1], i2 = g_invden[col * 3 + 2];
        const float q0 = qQ[col * 3 + 0], q1 = qQ[col * 3 + 1], q2 = qQ[col * 3 + 2];
        const float bj = bias[col];
        const float2 zz = unpack2(acc[j]);
        #pragma unroll
        for (int p = 0; p < 2; ++p) {
            const int row = row0 + p;
            const size_t off = (size_t)row * HH + col;
            const float xv = xwt[off];
            const float z  = (p ? zz.y : zz.x) + xv + bj;
            float d0 = z - c0, d1 = z - c1, d2 = z - c2;
            float mu0 = __expf(-d0 * d0 * i0);
            float mu1 = __expf(-d1 * d1 * i1);
            float mu2 = __expf(-d2 * d2 * i2);
            float num = mu0 * q0 + mu1 * q1 + mu2 * q2;
            float den = mu0 + mu1 + mu2;
            float g   = sigmoidf_fast(num / (den + 1e-8f));
            float ni  = tanhf(xv);
            float ho  = hin[off];
            hout[off] = (1.0f - g) * ho + g * ni;
        }
    }
}

// ------------------------------------------------------------------
// Final: logits[b] = h_final[b] . Wc + bc   (h_final = g_h[0] after T=128)
// ------------------------------------------------------------------
__global__ void final_kernel(const float* __restrict__ Wc,
                             const float* __restrict__ bc,
                             float* __restrict__ out)
{
    __shared__ float red[4];
    const int b = blockIdx.x;
    const int tid = threadIdx.x;   // 128 threads
    const float* hrow = g_h[0] + (size_t)b * HH;
    float s = 0.0f;
    #pragma unroll
    for (int h = tid; h < HH; h += 128) s += hrow[h] * Wc[h];
    #pragma unroll
    for (int o = 16; o > 0; o >>= 1) s += __shfl_down_sync(0xffffffffu, s, o);
    if ((tid & 31) == 0) red[tid >> 5] = s;
    __syncthreads();
    if (tid == 0) out[b] = red[0] + red[1] + red[2] + red[3] + bc[0];
}

// ------------------------------------------------------------------
// Launch
// Inputs: 0:x 1:theta 2:Wx 3:Wh 4:b 5:c 6:sigma 7:q 8:Wc 9:bc
// Output: [0..511] logits, [512..767] weights
// ------------------------------------------------------------------
extern "C" void kernel_launch(void* const* d_in, const int* in_sizes, int n_in,
                              void* d_out, int out_size)
{
    const float* x     = (const float*)d_in[0];
    const float* theta = (const float*)d_in[1];
    const float* Wx    = (const float*)d_in[2];
    const float* Wh    = (const float*)d_in[3];
    const float* bias  = (const float*)d_in[4];
    const float* c     = (const float*)d_in[5];
    const float* sigma = (const float*)d_in[6];
    const float* q     = (const float*)d_in[7];
    const float* Wc    = (const float*)d_in[8];
    const float* bc    = (const float*)d_in[9];
    float* out = (float*)d_out;

    // prep: covers max(B*H, F*H) = 262144 elements
    prep_kernel<<<(BB * HH + 255) / 256, 256>>>(theta, Wx, sigma, out);

    // xw = x @ (w*Wx), stored [T][B][H]
    gemm1_kernel<<<dim3((BB * TT) / 128, HH / 128), 256>>>(x);

    // sequential recurrence
    for (int t = 0; t < TT; ++t)
        step_kernel<<<dim3(BB / 32, HH / 64), 256>>>(Wh, bias, c, q, t);

    // classifier
    final_kernel<<<BB, 128>>>(Wc, bc, out);
}